// round 1
// baseline (speedup 1.0000x reference)
#include <cuda_runtime.h>

// MultiBCE collapsed form:
//   total = sum_{b,c} e(b,c) * w(c)
//   e(b,c) = -max(log(arg), -100), arg = y_true ? y_pred : 1 - y_pred
//   w(c)   = (1/C) * sum_h lam[h] * La[h,c]
// Masked (La=0) entries contribute exactly 0 in the reference (log clamp
// makes bce=0 there), so folding the mask into w(c) is exact.

#define BB 512
#define HH 8
#define CC 8192

__device__ float g_wneg[CC];  // -w(c), so acc = fma(clamped_log, wneg, acc)

__global__ void prep_kernel(const float* __restrict__ La,
                            const float* __restrict__ lam,
                            float* __restrict__ out) {
    int c = blockIdx.x * blockDim.x + threadIdx.x;
    if (c == 0) *out = 0.0f;  // d_out is poisoned; zero it before atomics
    if (c < CC) {
        float s = 0.0f;
#pragma unroll
        for (int h = 0; h < HH; ++h)
            s += lam[h] * La[h * CC + c];
        g_wneg[c] = -s * (1.0f / (float)CC);
    }
}

__global__ void __launch_bounds__(256)
bce_reduce_kernel(const float4* __restrict__ yp4,
                  const float4* __restrict__ yt4,
                  float* __restrict__ out) {
    const int N4 = (BB * CC) / 4;               // 1,048,576 float4 groups
    const float4* __restrict__ w4 = (const float4*)g_wneg;

    float acc = 0.0f;
    for (int i = blockIdx.x * blockDim.x + threadIdx.x; i < N4;
         i += gridDim.x * blockDim.x) {
        float4 p = yp4[i];
        float4 t = yt4[i];
        float4 w = w4[i & (CC / 4 - 1)];        // column index = i mod 2048

        // arg = yt ? yp : 1-yp  (yt is exactly 0.0 or 1.0)
        float a0 = (t.x != 0.0f) ? p.x : 1.0f - p.x;
        float a1 = (t.y != 0.0f) ? p.y : 1.0f - p.y;
        float a2 = (t.z != 0.0f) ? p.z : 1.0f - p.z;
        float a3 = (t.w != 0.0f) ? p.w : 1.0f - p.w;

        // __logf(0) = -inf -> fmaxf gives -100, matching the torch clamp.
        float l0 = fmaxf(__logf(a0), -100.0f);
        float l1 = fmaxf(__logf(a1), -100.0f);
        float l2 = fmaxf(__logf(a2), -100.0f);
        float l3 = fmaxf(__logf(a3), -100.0f);

        acc = fmaf(l0, w.x, acc);
        acc = fmaf(l1, w.y, acc);
        acc = fmaf(l2, w.z, acc);
        acc = fmaf(l3, w.w, acc);
    }

    // warp reduce
#pragma unroll
    for (int o = 16; o > 0; o >>= 1)
        acc += __shfl_down_sync(0xFFFFFFFFu, acc, o);

    __shared__ float smem[8];
    int lane = threadIdx.x & 31;
    int wid  = threadIdx.x >> 5;
    if (lane == 0) smem[wid] = acc;
    __syncthreads();
    if (wid == 0) {
        acc = (lane < (int)(blockDim.x >> 5)) ? smem[lane] : 0.0f;
#pragma unroll
        for (int o = 4; o > 0; o >>= 1)
            acc += __shfl_down_sync(0xFFFFFFFFu, acc, o);
        if (lane == 0) atomicAdd(out, acc);
    }
}

extern "C" void kernel_launch(void* const* d_in, const int* in_sizes, int n_in,
                              void* d_out, int out_size) {
    const float* y_pred = (const float*)d_in[0];  // [512, 8192] f32
    const float* y_true = (const float*)d_in[1];  // [512, 8192] f32
    const float* La     = (const float*)d_in[2];  // [8, 8192]   f32
    const float* lam    = (const float*)d_in[3];  // [8]         f32
    float* out = (float*)d_out;

    prep_kernel<<<(CC + 255) / 256, 256>>>(La, lam, out);

    // 592 blocks = 4 CTAs/SM on 148 SMs -> 8 warps/SMSP, plenty to hide
    // MUFU latency; each thread walks ~7 float4 groups.
    bce_reduce_kernel<<<592, 256>>>((const float4*)y_pred,
                                    (const float4*)y_true, out);
}